// round 15
// baseline (speedup 1.0000x reference)
#include <cuda_runtime.h>
#include <cuda_bf16.h>
#include <cuda_fp16.h>

// Problem dims
#define NBATCH 2
#define NC 64
#define NT 16
#define NH 64
#define NW 64
#define PLANE 4096                    // NH*NW
#define SROW 72                       // padded smem row stride (floats)

typedef unsigned long long ull;

// ---------------- scratch (__device__ globals; no runtime allocation) ------
__device__ float2  g_QA[NC * NT * NH * 3];                   // 1.5 MB
__device__ float2  g_QB[NC * NT * NH * 3];                   // 1.5 MB
__device__ __half2 g_gu [(size_t)NBATCH * NC * NT * PLANE];  // 33.5 MB fp16 (g,u)
__device__ float2  g_xT2[(size_t)NBATCH * 32 * NT * PLANE];  // 33.5 MB (x pairs, then y pairs)
__device__ float2  g_X  [(size_t)NBATCH * NC * NT * PLANE];  // 67 MB (X then h_f in place)

// ---------------- twiddle table (uniform compile-time indices only) --------
__constant__ float2 gW64[32] = {
    { 1.00000000f, -0.00000000f}, { 0.99518473f, -0.09801714f},
    { 0.98078528f, -0.19509032f}, { 0.95694034f, -0.29028468f},
    { 0.92387953f, -0.38268343f}, { 0.88192126f, -0.47139674f},
    { 0.83146961f, -0.55557023f}, { 0.77301045f, -0.63439328f},
    { 0.70710678f, -0.70710678f}, { 0.63439328f, -0.77301045f},
    { 0.55557023f, -0.83146961f}, { 0.47139674f, -0.88192126f},
    { 0.38268343f, -0.92387953f}, { 0.29028468f, -0.95694034f},
    { 0.19509032f, -0.98078528f}, { 0.09801714f, -0.99518473f},
    { 0.00000000f, -1.00000000f}, {-0.09801714f, -0.99518473f},
    {-0.19509032f, -0.98078528f}, {-0.29028468f, -0.95694034f},
    {-0.38268343f, -0.92387953f}, {-0.47139674f, -0.88192126f},
    {-0.55557023f, -0.83146961f}, {-0.63439328f, -0.77301045f},
    {-0.70710678f, -0.70710678f}, {-0.77301045f, -0.63439328f},
    {-0.83146961f, -0.55557023f}, {-0.88192126f, -0.47139674f},
    {-0.92387953f, -0.38268343f}, {-0.95694034f, -0.29028468f},
    {-0.98078528f, -0.19509032f}, {-0.99518473f, -0.09801714f}
};

// ---------------- complex helpers ------------------------------------------
__device__ __forceinline__ float2 cadd(float2 a, float2 b){ return make_float2(a.x+b.x, a.y+b.y); }
__device__ __forceinline__ float2 csub(float2 a, float2 b){ return make_float2(a.x-b.x, a.y-b.y); }
__device__ __forceinline__ float2 cmul(float2 a, float2 b){
    return make_float2(a.x*b.x - a.y*b.y, a.x*b.y + a.y*b.x);
}

template<int SGN>
__device__ __forceinline__ float2 tw64c(int i){       // constant table, uniform idx
    float2 t = gW64[i];
    if (SGN < 0) t.y = -t.y;
    return t;
}

// padded column address: avoids bank conflicts for stride-8 AND contiguous-8
__device__ __forceinline__ int swz(int w){ return w + (w >> 3); }

// ---------------- f32x2 packed FMA helpers (GEMV only) ---------------------
__device__ __forceinline__ ull pk2(float a, float b){
    ull r; asm("mov.b64 %0, {%1,%2};" : "=l"(r) : "f"(a), "f"(b)); return r;
}
__device__ __forceinline__ float2 upk2(ull v){
    float2 f; asm("mov.b64 {%0,%1}, %2;" : "=f"(f.x), "=f"(f.y) : "l"(v)); return f;
}
__device__ __forceinline__ ull ffma2(ull a, ull b, ull c){
    ull d; asm("fma.rn.f32x2 %0, %1, %2, %3;" : "=l"(d) : "l"(a), "l"(b), "l"(c)); return d;
}

// ---------------- register FFT8 (natural in/out) ---------------------------
template<int SGN>
__device__ __forceinline__ void fft8(float2 v[8]){
    #pragma unroll
    for (int half = 4; half >= 1; half >>= 1){
        #pragma unroll
        for (int base = 0; base < 8; base += 2*half){
            #pragma unroll
            for (int j = 0; j < half; j++){
                float2 a = v[base+j], b = v[base+j+half];
                v[base+j] = cadd(a, b);
                v[base+j+half] = cmul(csub(a, b), tw64c<SGN>(j * (32/half)));
            }
        }
    }
    float2 t;
    t=v[1]; v[1]=v[4]; v[4]=t;     // 3-bit reversal
    t=v[3]; v[3]=v[6]; v[6]=t;
}

// ---------------- register FFT16 (natural in, natural out) -----------------
template<int SGN>
__device__ __forceinline__ void fft16(float2 v[16]){
    #pragma unroll
    for (int half = 8; half >= 1; half >>= 1){
        #pragma unroll
        for (int base = 0; base < 16; base += 2*half){
            #pragma unroll
            for (int j = 0; j < half; j++){
                float2 a = v[base+j], b = v[base+j+half];
                v[base+j] = cadd(a, b);
                v[base+j+half] = cmul(csub(a, b), tw64c<SGN>(j * (32/half)));
            }
        }
    }
    float2 t;
    t=v[1];  v[1]=v[8];   v[8]=t;
    t=v[2];  v[2]=v[4];   v[4]=t;
    t=v[3];  v[3]=v[12];  v[12]=t;
    t=v[5];  v[5]=v[10];  v[10]=t;
    t=v[7];  v[7]=v[14];  v[14]=t;
    t=v[11]; v[11]=v[13]; v[13]=t;
}

// ---------------- 2D FFT64x64 in smem via radix-8 x radix-8 ----------------
template<int SGN>
__device__ __forceinline__ void fft2d_smem(float* sre, float* sim, int tid){
    const float sgn = (SGN > 0) ? -1.0f : 1.0f;
    float ss, cc;

    // ---- row pass: 8 threads per row (same warp), rows tid>>3, +32 --------
    int n2 = tid & 7, rg = tid >> 3;
    sincospif(sgn * (float)n2 / 32.0f, &ss, &cc);
    float2 twn2 = make_float2(cc, ss);           // W64^{±n2}
    #pragma unroll
    for (int it = 0; it < 2; it++){
        int row = it*32 + rg;
        float* rre = sre + row*SROW;
        float* rim = sim + row*SROW;
        float2 v[8];
        #pragma unroll
        for (int j = 0; j < 8; j++){
            int cI = swz(8*j + n2);
            v[j] = make_float2(rre[cI], rim[cI]);
        }
        fft8<SGN>(v);
        {   // v[k1] *= W64^{±n2*k1}
            float2 w = twn2;
            v[1] = cmul(v[1], w);
            #pragma unroll
            for (int k = 2; k < 8; k++){ w = cmul(w, twn2); v[k] = cmul(v[k], w); }
        }
        __syncwarp();
        #pragma unroll
        for (int j = 0; j < 8; j++){                 // B[n2][k1=j] at col 8*n2+j
            int cI = swz(8*n2 + j);
            rre[cI] = v[j].x; rim[cI] = v[j].y;
        }
        __syncwarp();
        #pragma unroll
        for (int j = 0; j < 8; j++){                 // thread acts as k1=n2
            int cI = swz(8*j + n2);                  // B[n2'=j][k1]
            v[j] = make_float2(rre[cI], rim[cI]);
        }
        fft8<SGN>(v);
        #pragma unroll
        for (int j = 0; j < 8; j++){                 // X[8*k2+k1], k2=j
            int cI = swz(8*j + n2);
            rre[cI] = v[j].x; rim[cI] = v[j].y;
        }
    }
    __syncthreads();

    // ---- column pass: cols across the warp (tid&31), n2 = tid>>5 ----------
    int cn2 = tid >> 5, cg = tid & 31;
    sincospif(sgn * (float)cn2 / 32.0f, &ss, &cc);
    float2 twc = make_float2(cc, ss);
    #pragma unroll
    for (int it = 0; it < 2; it++){
        int cph = swz(it*32 + cg);
        float2 v[8];
        #pragma unroll
        for (int j = 0; j < 8; j++){
            int r = 8*j + cn2;
            v[j] = make_float2(sre[r*SROW + cph], sim[r*SROW + cph]);
        }
        fft8<SGN>(v);
        {
            float2 w = twc;
            v[1] = cmul(v[1], w);
            #pragma unroll
            for (int k = 2; k < 8; k++){ w = cmul(w, twc); v[k] = cmul(v[k], w); }
        }
        __syncthreads();
        #pragma unroll
        for (int j = 0; j < 8; j++){                 // B at row 8*cn2+j
            int r = 8*cn2 + j;
            sre[r*SROW + cph] = v[j].x; sim[r*SROW + cph] = v[j].y;
        }
        __syncthreads();
        #pragma unroll
        for (int j = 0; j < 8; j++){                 // rows 8*j+cn2 (exclusive)
            int r = 8*j + cn2;
            v[j] = make_float2(sre[r*SROW + cph], sim[r*SROW + cph]);
        }
        fft8<SGN>(v);
        #pragma unroll
        for (int j = 0; j < 8; j++){
            int r = 8*j + cn2;
            sre[r*SROW + cph] = v[j].x; sim[r*SROW + cph] = v[j].y;
        }
    }
    __syncthreads();
}

__device__ __forceinline__ float sigmoidf_(float v){ return 1.0f / (1.0f + __expf(-v)); }
__device__ __forceinline__ float softplusf_(float v){
    return fmaxf(v, 0.0f) + log1pf(__expf(-fabsf(v)));
}

// ============ T0: transpose x (b,t,h,w,c) -> xT2 (b,cp,t,h,w) float2 pairs =
__global__ __launch_bounds__(256) void t0(const float* __restrict__ x){
    __shared__ float s[64*65];           // s[c][w]
    int blk = blockIdx.x;                // (b,t,h)
    int b = blk >> 10, t = (blk >> 6) & 15, h = blk & 63;
    size_t xbase = (size_t)blk * PLANE;
    int tid = threadIdx.x;

    #pragma unroll
    for (int i = 0; i < 16; i++){
        int idx = tid + i*256;           // idx = w*64 + c
        s[(idx & 63)*65 + (idx >> 6)] = x[xbase + idx];
    }
    __syncthreads();
    #pragma unroll
    for (int i = 0; i < 8; i++){
        int idx = tid + i*256;           // idx = cp*64 + w  (cp 0..31)
        int cp = idx >> 6, w = idx & 63;
        g_xT2[(((size_t)(b*32 + cp)*NT + t) * PLANE) + h*64 + w] =
            make_float2(s[(2*cp)*65 + w], s[(2*cp+1)*65 + w]);
    }
}

// ============ K1b: delta GEMV + gates -> fp16 gu  (+ merged K0 tail) =======
__global__ __launch_bounds__(256) void k1b(
    const float* __restrict__ x,  const float* __restrict__ dW,
    const float* __restrict__ db, const float* __restrict__ ib,
    const float* __restrict__ isc, const float* __restrict__ fb,
    const float* __restrict__ fs, const float* __restrict__ Ak,
    const float* __restrict__ Bk)
{
    __shared__ float  xs[64*65];         // xs[w][c]
    __shared__ float4 Ws4[64*17];        // Ws4[c][q]
    int tid = threadIdx.x;

    // ---- merged K0: blocks 2048..2815 build Q tables ----
    if (blockIdx.x >= 2048){
        int i = (blockIdx.x - 2048)*256 + tid;     // < 196608 = 64*16*64*3
        int kw = i % 3, h = (i/3) % NH, t = (i/192) % NT, c = i/(192*NT);
        float2 aA = make_float2(0.f,0.f), aB = make_float2(0.f,0.f);
        #pragma unroll
        for (int kt = 0; kt < 3; kt++){
            float st, ct;
            sincospif(-2.0f * (float)t * (float)(kt-1) / (float)NT, &st, &ct);
            float2 et = make_float2(ct, st);
            #pragma unroll
            for (int kh = 0; kh < 3; kh++){
                float sh, ch;
                sincospif(-2.0f * (float)h * (float)(kh-1) / (float)NH, &sh, &ch);
                float2 e = cmul(et, make_float2(ch, sh));
                float ka = Ak[((c*3+kt)*3+kh)*3+kw];
                float kb = Bk[((c*3+kt)*3+kh)*3+kw];
                aA.x += ka*e.x; aA.y += ka*e.y;
                aB.x += kb*e.x; aB.y += kb*e.y;
            }
        }
        g_QA[i] = aA; g_QB[i] = aB;
        return;
    }

    int blk = blockIdx.x;
    int b = blk >> 10, t = (blk >> 6) & 15, h = blk & 63;
    size_t xbase = (size_t)blk * PLANE;

    const float4* dW4 = reinterpret_cast<const float4*>(dW);
    #pragma unroll
    for (int i = 0; i < 4; i++){
        int j = tid + i*256;
        Ws4[(j >> 4)*17 + (j & 15)] = dW4[j];
    }
    #pragma unroll
    for (int i = 0; i < 16; i++){
        int idx = tid + i*256;           // idx = w*64 + c
        xs[(idx >> 6)*65 + (idx & 63)] = x[xbase + idx];
    }
    __syncthreads();

    int w   = tid & 63;
    int dg  = tid >> 6;
    int ddb = dg << 4;

    ull acc[8];
    #pragma unroll
    for (int j = 0; j < 8; j++) acc[j] = pk2(__ldg(&db[ddb+2*j]), __ldg(&db[ddb+2*j+1]));

    const float* xrow = &xs[w*65];
    #pragma unroll 4
    for (int c = 0; c < 64; c++){
        float xv = xrow[c];
        ull xp = pk2(xv, xv);
        const float4* wr = &Ws4[c*17 + dg*4];
        float4 w0 = wr[0], w1 = wr[1], w2 = wr[2], w3 = wr[3];
        acc[0] = ffma2(xp, pk2(w0.x, w0.y), acc[0]);
        acc[1] = ffma2(xp, pk2(w0.z, w0.w), acc[1]);
        acc[2] = ffma2(xp, pk2(w1.x, w1.y), acc[2]);
        acc[3] = ffma2(xp, pk2(w1.z, w1.w), acc[3]);
        acc[4] = ffma2(xp, pk2(w2.x, w2.y), acc[4]);
        acc[5] = ffma2(xp, pk2(w2.z, w2.w), acc[5]);
        acc[6] = ffma2(xp, pk2(w3.x, w3.y), acc[6]);
        acc[7] = ffma2(xp, pk2(w3.z, w3.w), acc[7]);
    }

    #pragma unroll
    for (int jj = 0; jj < 8; jj++){
        float2 dp = upk2(acc[jj]);
        #pragma unroll
        for (int k = 0; k < 2; k++){
            int ch = ddb + 2*jj + k;
            float dv = k ? dp.y : dp.x;
            float delta = softplusf_(dv);
            float xv = xs[w*65 + ch];
            float gv = sigmoidf_(__ldg(&fb[ch]) + __ldg(&fs[ch]) * xv);
            float uv = sigmoidf_(__ldg(&ib[ch]) + __ldg(&isc[ch]) * xv) * delta;
            size_t o = (((size_t)(b*NC + ch)*NT + t) * PLANE) + h*64 + w;
            g_gu[o] = __floats2half2_rn(gv, uv);
        }
    }
}

// ============ K2p: paired real 2D FFT (radix-8) + Hermitian unpack =========
__global__ __launch_bounds__(256) void k2p(){
    __shared__ float sre[64*SROW];
    __shared__ float sim[64*SROW];
    int blk = blockIdx.x;                // (b,t,cp)
    int cp = blk & 31, t = (blk >> 5) & 15, b = blk >> 9;
    int c0 = cp*2;
    size_t base0 = ((size_t)((b*NC + c0)*NT + t)) * PLANE;     // X planes
    size_t base1 = base0 + (size_t)NT*PLANE;
    size_t base2 = ((size_t)((b*32 + cp)*NT + t)) * PLANE;     // xT2 plane
    int tid = threadIdx.x;

    #pragma unroll
    for (int i = 0; i < 16; i++){
        int idx = tid + i*256; int h = idx>>6, w = idx&63;
        float2 v = g_xT2[base2 + idx];
        int a = h*SROW + swz(w);
        sre[a] = v.x;
        sim[a] = v.y;
    }
    __syncthreads();

    fft2d_smem<1>(sre, sim, tid);

    // X0 = (Z[k]+conj(Z[-k]))/2, X1 = (Z[k]-conj(Z[-k]))/(2i)
    #pragma unroll
    for (int i = 0; i < 16; i++){
        int idx = tid + i*256; int kh = idx>>6, kw = idx&63;
        int mh = (NH - kh) & 63, mw = (NW - kw) & 63;
        int a  = kh*SROW + swz(kw);
        int m  = mh*SROW + swz(mw);
        float zr = sre[a], zi = sim[a];
        float mr = sre[m], mi = sim[m];
        g_X[base0 + idx] = make_float2(0.5f*(zr + mr), 0.5f*(zi - mi));
        g_X[base1 + idx] = make_float2(0.5f*(zi + mi), 0.5f*(mr - zr));
    }
}

// ============ K3: FFT16 over T + gated scan + iFFT16 (S/D filter recon) ====
// sQ* slots after transform: [qb]=S=q0+q2, [qb+1]=q1, [qb+2]=D=q0-q2.
// af = cmul(q0,ep)+q1+cmul(q2,conj(ep))
//    = (S.x*cw - D.y*sw + q1.x,  D.x*sw + S.y*cw + q1.y)
__global__ __launch_bounds__(256, 4) void k3(){
    __shared__ float2 sQA[192];          // [t][h'][3]
    __shared__ float2 sQB[192];
    int blk = blockIdx.x;
    int tid = threadIdx.x;
    int hwblk = blk & 15;
    int c = (blk >> 4) & 63;
    int b = blk >> 10;
    int hw = hwblk*256 + tid;
    int w  = hw & 63;
    int hp = tid >> 6;
    int h0 = hwblk * 4;

    if (tid < 192){
        int kw = tid % 3, hh = (tid/3) & 3, t = tid / 12;
        int gidx = ((c*NT + t)*NH + (h0 + hh))*3 + kw;
        sQA[tid] = g_QA[gidx];
        sQB[tid] = g_QB[gidx];
    }
    __syncthreads();
    if (tid < 64){                       // one thread per (t,hh): S/D transform
        int qb = tid * 3;
        float2 a0 = sQA[qb], a2 = sQA[qb+2];
        sQA[qb]   = cadd(a0, a2);
        sQA[qb+2] = csub(a0, a2);
        float2 b0 = sQB[qb], b2 = sQB[qb+2];
        sQB[qb]   = cadd(b0, b2);
        sQB[qb+2] = csub(b0, b2);
    }
    __syncthreads();

    float sw, cw;
    sincospif(2.0f * (float)w / (float)NW, &sw, &cw);

    size_t xbase = ((size_t)(b*NC + c) * NT) * PLANE + hw;

    float2 v[16];
    #pragma unroll
    for (int t = 0; t < 16; t++) v[t] = g_X[xbase + (size_t)t*PLANE];
    fft16<1>(v);

    float2 hst = make_float2(0.f, 0.f);
    #pragma unroll
    for (int t = 0; t < 16; t++){
        size_t o = (size_t)t * PLANE;
        int qb = t*12 + hp*3;
        float2 SA = sQA[qb], QA1 = sQA[qb+1], DA = sQA[qb+2];
        float2 SB = sQB[qb], QB1 = sQB[qb+1], DB = sQB[qb+2];
        float2 af = make_float2(fmaf(SA.x, cw, fmaf(-DA.y, sw, QA1.x)),
                                fmaf(DA.x, sw, fmaf( SA.y, cw, QA1.y)));
        float2 bf = make_float2(fmaf(SB.x, cw, fmaf(-DB.y, sw, QB1.x)),
                                fmaf(DB.x, sw, fmaf( SB.y, cw, QB1.y)));
        float2 gu = __half22float2(g_gu[xbase + o]);
        float2 a  = make_float2(af.x*gu.x, af.y*gu.x);
        float2 bb = cmul(bf, v[t]);
        bb.x *= gu.y; bb.y *= gu.y;
        hst = cadd(cmul(a, hst), bb);
        v[t] = hst;
    }
    fft16<-1>(v);
    #pragma unroll
    for (int t = 0; t < 16; t++) g_X[xbase + (size_t)t*PLANE] = v[t];
}

// ============ K4p: paired inverse 2D FFT (radix-8) -> yT2 pairs ============
__global__ __launch_bounds__(256) void k4p(){
    __shared__ float sre[64*SROW];
    __shared__ float sim[64*SROW];
    int blk = blockIdx.x;
    int cp = blk & 31, t = (blk >> 5) & 15, b = blk >> 9;
    int c0 = cp*2;
    size_t base0 = ((size_t)((b*NC + c0)*NT + t)) * PLANE;
    size_t base1 = base0 + (size_t)NT*PLANE;
    size_t base2 = ((size_t)((b*32 + cp)*NT + t)) * PLANE;     // yT2 plane
    int tid = threadIdx.x;

    // load + Hermitian projection (mirror reads are L2 hits)
    #pragma unroll
    for (int i = 0; i < 16; i++){
        int idx = tid + i*256; int kh = idx>>6, kw = idx&63;
        int mh = (NH - kh) & 63, mw = (NW - kw) & 63;
        int midx = mh*64 + mw;
        float2 A  = g_X[base0 + idx];
        float2 Bm = g_X[base0 + midx];
        float2 C  = g_X[base1 + idx];
        float2 Dm = g_X[base1 + midx];
        int a = kh*SROW + swz(kw);
        sre[a] = A.x + Bm.x - C.y + Dm.y;
        sim[a] = A.y - Bm.y + C.x + Dm.x;
    }
    __syncthreads();

    fft2d_smem<-1>(sre, sim, tid);

    const float sc = 0.5f / 65536.0f;    // 1/(2*T*H*W): Herm 1/2 folded in
    #pragma unroll
    for (int i = 0; i < 16; i++){
        int idx = tid + i*256; int h = idx>>6, w = idx&63;
        int a = h*SROW + swz(w);
        g_xT2[base2 + idx] = make_float2(sre[a] * sc, sim[a] * sc);
    }
}

// ============ K5: transpose yT2 (b,cp,t,h,w) -> out (b,t,h,w,c) ============
__global__ __launch_bounds__(256) void k5(float* __restrict__ out){
    __shared__ float2 s2[32*65];
    int blk = blockIdx.x;                // (b,t,h)
    int b = blk >> 10, t = (blk >> 6) & 15, h = blk & 63;
    int tid = threadIdx.x;
    #pragma unroll
    for (int i = 0; i < 8; i++){
        int idx = tid + i*256;           // idx = cp*64 + w
        int cp = idx >> 6, w = idx & 63;
        s2[cp*65 + w] = g_xT2[(((size_t)(b*32 + cp)*NT + t) * PLANE) + h*64 + w];
    }
    __syncthreads();
    float2* out2 = reinterpret_cast<float2*>(out);
    size_t obase2 = (size_t)blk * 2048;
    #pragma unroll
    for (int i = 0; i < 8; i++){
        int idx = tid + i*256;           // idx = w*32 + cp
        int w = idx >> 5, cp = idx & 31;
        out2[obase2 + (size_t)w*32 + cp] = s2[cp*65 + w];
    }
}

// ---------------- side-stream objects (host-side, created at static init) --
struct SideStream {
    cudaStream_t s1 = nullptr;
    cudaEvent_t  e0 = nullptr, e1 = nullptr;
    bool ok = false;
    SideStream(){
        ok = (cudaStreamCreateWithFlags(&s1, cudaStreamNonBlocking) == cudaSuccess)
          && (cudaEventCreateWithFlags(&e0, cudaEventDisableTiming) == cudaSuccess)
          && (cudaEventCreateWithFlags(&e1, cudaEventDisableTiming) == cudaSuccess);
    }
};
static SideStream g_ss;

// ===========================================================================
extern "C" void kernel_launch(void* const* d_in, const int* in_sizes, int n_in,
                              void* d_out, int out_size)
{
    const float* x   = (const float*)d_in[0];
    const float* Ak  = (const float*)d_in[1];
    const float* Bk  = (const float*)d_in[2];
    const float* fb  = (const float*)d_in[3];
    const float* fs  = (const float*)d_in[4];
    const float* ib  = (const float*)d_in[5];
    const float* isc = (const float*)d_in[6];
    const float* dW  = (const float*)d_in[7];
    const float* db  = (const float*)d_in[8];
    float* out = (float*)d_out;

    if (g_ss.ok){
        // fork: k1b (+merged k0) depends only on inputs; overlap with t0/k2p
        cudaEventRecord(g_ss.e0, 0);
        cudaStreamWaitEvent(g_ss.s1, g_ss.e0, 0);
        k1b<<<2816, 256, 0, g_ss.s1>>>(x, dW, db, ib, isc, fb, fs, Ak, Bk);
        cudaEventRecord(g_ss.e1, g_ss.s1);

        t0 <<<2048, 256>>>(x);
        k2p<<<1024, 256>>>();
        cudaStreamWaitEvent(0, g_ss.e1, 0);   // join before k3 (needs gu, QA/QB)
    } else {
        k1b<<<2816, 256>>>(x, dW, db, ib, isc, fb, fs, Ak, Bk);
        t0 <<<2048, 256>>>(x);
        k2p<<<1024, 256>>>();
    }
    k3 <<<2048, 256>>>();
    k4p<<<1024, 256>>>();
    k5 <<<2048, 256>>>(out);
}

// round 16
// speedup vs baseline: 1.0520x; 1.0520x over previous
#include <cuda_runtime.h>
#include <cuda_bf16.h>
#include <cuda_fp16.h>

// Problem dims
#define NBATCH 2
#define NC 64
#define NT 16
#define NH 64
#define NW 64
#define PLANE 4096                    // NH*NW
#define SROW 72                       // padded smem row stride (floats)

typedef unsigned long long ull;

// ---------------- scratch (__device__ globals; no runtime allocation) ------
__device__ float2  g_QA[NC * NT * NH * 3];                   // 1.5 MB
__device__ float2  g_QB[NC * NT * NH * 3];                   // 1.5 MB
__device__ __half2 g_gu [(size_t)NBATCH * NC * NT * PLANE];  // 33.5 MB fp16 (g,u)
__device__ float2  g_xT2[(size_t)NBATCH * 32 * NT * PLANE];  // 33.5 MB (x pairs, then y pairs)
__device__ float2  g_X  [(size_t)NBATCH * NC * NT * PLANE];  // 67 MB (X then h_f in place)

// ---------------- twiddle table (uniform compile-time indices only) --------
__constant__ float2 gW64[32] = {
    { 1.00000000f, -0.00000000f}, { 0.99518473f, -0.09801714f},
    { 0.98078528f, -0.19509032f}, { 0.95694034f, -0.29028468f},
    { 0.92387953f, -0.38268343f}, { 0.88192126f, -0.47139674f},
    { 0.83146961f, -0.55557023f}, { 0.77301045f, -0.63439328f},
    { 0.70710678f, -0.70710678f}, { 0.63439328f, -0.77301045f},
    { 0.55557023f, -0.83146961f}, { 0.47139674f, -0.88192126f},
    { 0.38268343f, -0.92387953f}, { 0.29028468f, -0.95694034f},
    { 0.19509032f, -0.98078528f}, { 0.09801714f, -0.99518473f},
    { 0.00000000f, -1.00000000f}, {-0.09801714f, -0.99518473f},
    {-0.19509032f, -0.98078528f}, {-0.29028468f, -0.95694034f},
    {-0.38268343f, -0.92387953f}, {-0.47139674f, -0.88192126f},
    {-0.55557023f, -0.83146961f}, {-0.63439328f, -0.77301045f},
    {-0.70710678f, -0.70710678f}, {-0.77301045f, -0.63439328f},
    {-0.83146961f, -0.55557023f}, {-0.88192126f, -0.47139674f},
    {-0.92387953f, -0.38268343f}, {-0.95694034f, -0.29028468f},
    {-0.98078528f, -0.19509032f}, {-0.99518473f, -0.09801714f}
};

// ---------------- complex helpers ------------------------------------------
__device__ __forceinline__ float2 cadd(float2 a, float2 b){ return make_float2(a.x+b.x, a.y+b.y); }
__device__ __forceinline__ float2 csub(float2 a, float2 b){ return make_float2(a.x-b.x, a.y-b.y); }
__device__ __forceinline__ float2 cmul(float2 a, float2 b){
    return make_float2(a.x*b.x - a.y*b.y, a.x*b.y + a.y*b.x);
}

template<int SGN>
__device__ __forceinline__ float2 tw64c(int i){       // constant table, uniform idx
    float2 t = gW64[i];
    if (SGN < 0) t.y = -t.y;
    return t;
}

// padded column address: avoids bank conflicts for stride-8 AND contiguous-8
__device__ __forceinline__ int swz(int w){ return w + (w >> 3); }

// ---------------- f32x2 packed FMA helpers (GEMV only) ---------------------
__device__ __forceinline__ ull pk2(float a, float b){
    ull r; asm("mov.b64 %0, {%1,%2};" : "=l"(r) : "f"(a), "f"(b)); return r;
}
__device__ __forceinline__ float2 upk2(ull v){
    float2 f; asm("mov.b64 {%0,%1}, %2;" : "=f"(f.x), "=f"(f.y) : "l"(v)); return f;
}
__device__ __forceinline__ ull ffma2(ull a, ull b, ull c){
    ull d; asm("fma.rn.f32x2 %0, %1, %2, %3;" : "=l"(d) : "l"(a), "l"(b), "l"(c)); return d;
}

// ---------------- register FFT8 (natural in/out) ---------------------------
template<int SGN>
__device__ __forceinline__ void fft8(float2 v[8]){
    #pragma unroll
    for (int half = 4; half >= 1; half >>= 1){
        #pragma unroll
        for (int base = 0; base < 8; base += 2*half){
            #pragma unroll
            for (int j = 0; j < half; j++){
                float2 a = v[base+j], b = v[base+j+half];
                v[base+j] = cadd(a, b);
                v[base+j+half] = cmul(csub(a, b), tw64c<SGN>(j * (32/half)));
            }
        }
    }
    float2 t;
    t=v[1]; v[1]=v[4]; v[4]=t;     // 3-bit reversal
    t=v[3]; v[3]=v[6]; v[6]=t;
}

// ---------------- register FFT16 (natural in, natural out) -----------------
template<int SGN>
__device__ __forceinline__ void fft16(float2 v[16]){
    #pragma unroll
    for (int half = 8; half >= 1; half >>= 1){
        #pragma unroll
        for (int base = 0; base < 16; base += 2*half){
            #pragma unroll
            for (int j = 0; j < half; j++){
                float2 a = v[base+j], b = v[base+j+half];
                v[base+j] = cadd(a, b);
                v[base+j+half] = cmul(csub(a, b), tw64c<SGN>(j * (32/half)));
            }
        }
    }
    float2 t;
    t=v[1];  v[1]=v[8];   v[8]=t;
    t=v[2];  v[2]=v[4];   v[4]=t;
    t=v[3];  v[3]=v[12];  v[12]=t;
    t=v[5];  v[5]=v[10];  v[10]=t;
    t=v[7];  v[7]=v[14];  v[14]=t;
    t=v[11]; v[11]=v[13]; v[13]=t;
}

// ---------------- 2D FFT64x64 in smem via radix-8 x radix-8 ----------------
template<int SGN>
__device__ __forceinline__ void fft2d_smem(float* sre, float* sim, int tid){
    const float sgn = (SGN > 0) ? -1.0f : 1.0f;
    float ss, cc;

    // ---- row pass: 8 threads per row (same warp), rows tid>>3, +32 --------
    int n2 = tid & 7, rg = tid >> 3;
    sincospif(sgn * (float)n2 / 32.0f, &ss, &cc);
    float2 twn2 = make_float2(cc, ss);           // W64^{±n2}
    #pragma unroll
    for (int it = 0; it < 2; it++){
        int row = it*32 + rg;
        float* rre = sre + row*SROW;
        float* rim = sim + row*SROW;
        float2 v[8];
        #pragma unroll
        for (int j = 0; j < 8; j++){
            int cI = swz(8*j + n2);
            v[j] = make_float2(rre[cI], rim[cI]);
        }
        fft8<SGN>(v);
        {   // v[k1] *= W64^{±n2*k1}
            float2 w = twn2;
            v[1] = cmul(v[1], w);
            #pragma unroll
            for (int k = 2; k < 8; k++){ w = cmul(w, twn2); v[k] = cmul(v[k], w); }
        }
        __syncwarp();
        #pragma unroll
        for (int j = 0; j < 8; j++){                 // B[n2][k1=j] at col 8*n2+j
            int cI = swz(8*n2 + j);
            rre[cI] = v[j].x; rim[cI] = v[j].y;
        }
        __syncwarp();
        #pragma unroll
        for (int j = 0; j < 8; j++){                 // thread acts as k1=n2
            int cI = swz(8*j + n2);                  // B[n2'=j][k1]
            v[j] = make_float2(rre[cI], rim[cI]);
        }
        fft8<SGN>(v);
        #pragma unroll
        for (int j = 0; j < 8; j++){                 // X[8*k2+k1], k2=j
            int cI = swz(8*j + n2);
            rre[cI] = v[j].x; rim[cI] = v[j].y;
        }
    }
    __syncthreads();

    // ---- column pass: cols across the warp (tid&31), n2 = tid>>5 ----------
    int cn2 = tid >> 5, cg = tid & 31;
    sincospif(sgn * (float)cn2 / 32.0f, &ss, &cc);
    float2 twc = make_float2(cc, ss);
    #pragma unroll
    for (int it = 0; it < 2; it++){
        int cph = swz(it*32 + cg);
        float2 v[8];
        #pragma unroll
        for (int j = 0; j < 8; j++){
            int r = 8*j + cn2;
            v[j] = make_float2(sre[r*SROW + cph], sim[r*SROW + cph]);
        }
        fft8<SGN>(v);
        {
            float2 w = twc;
            v[1] = cmul(v[1], w);
            #pragma unroll
            for (int k = 2; k < 8; k++){ w = cmul(w, twc); v[k] = cmul(v[k], w); }
        }
        __syncthreads();
        #pragma unroll
        for (int j = 0; j < 8; j++){                 // B at row 8*cn2+j
            int r = 8*cn2 + j;
            sre[r*SROW + cph] = v[j].x; sim[r*SROW + cph] = v[j].y;
        }
        __syncthreads();
        #pragma unroll
        for (int j = 0; j < 8; j++){                 // rows 8*j+cn2 (exclusive)
            int r = 8*j + cn2;
            v[j] = make_float2(sre[r*SROW + cph], sim[r*SROW + cph]);
        }
        fft8<SGN>(v);
        #pragma unroll
        for (int j = 0; j < 8; j++){
            int r = 8*j + cn2;
            sre[r*SROW + cph] = v[j].x; sim[r*SROW + cph] = v[j].y;
        }
    }
    __syncthreads();
}

__device__ __forceinline__ float sigmoidf_(float v){ return 1.0f / (1.0f + __expf(-v)); }
__device__ __forceinline__ float softplusf_(float v){
    return fmaxf(v, 0.0f) + log1pf(__expf(-fabsf(v)));
}

// ============ T0: transpose x (b,t,h,w,c) -> xT2 (b,cp,t,h,w) float2 pairs =
__global__ __launch_bounds__(256) void t0(const float* __restrict__ x){
    __shared__ float s[64*65];           // s[c][w]
    int blk = blockIdx.x;                // (b,t,h)
    int b = blk >> 10, t = (blk >> 6) & 15, h = blk & 63;
    size_t xbase = (size_t)blk * PLANE;
    int tid = threadIdx.x;

    #pragma unroll
    for (int i = 0; i < 16; i++){
        int idx = tid + i*256;           // idx = w*64 + c
        s[(idx & 63)*65 + (idx >> 6)] = x[xbase + idx];
    }
    __syncthreads();
    #pragma unroll
    for (int i = 0; i < 8; i++){
        int idx = tid + i*256;           // idx = cp*64 + w  (cp 0..31)
        int cp = idx >> 6, w = idx & 63;
        g_xT2[(((size_t)(b*32 + cp)*NT + t) * PLANE) + h*64 + w] =
            make_float2(s[(2*cp)*65 + w], s[(2*cp+1)*65 + w]);
    }
}

// ============ K1b: delta GEMV + gates -> fp16 gu  (+ merged K0 tail) =======
__global__ __launch_bounds__(256) void k1b(
    const float* __restrict__ x,  const float* __restrict__ dW,
    const float* __restrict__ db, const float* __restrict__ ib,
    const float* __restrict__ isc, const float* __restrict__ fb,
    const float* __restrict__ fs, const float* __restrict__ Ak,
    const float* __restrict__ Bk)
{
    __shared__ float  xs[64*65];         // xs[w][c]
    __shared__ float4 Ws4[64*17];        // Ws4[c][q]
    int tid = threadIdx.x;

    // ---- merged K0: blocks 2048..2815 build Q tables ----
    if (blockIdx.x >= 2048){
        int i = (blockIdx.x - 2048)*256 + tid;     // < 196608 = 64*16*64*3
        int kw = i % 3, h = (i/3) % NH, t = (i/192) % NT, c = i/(192*NT);
        float2 aA = make_float2(0.f,0.f), aB = make_float2(0.f,0.f);
        #pragma unroll
        for (int kt = 0; kt < 3; kt++){
            float st, ct;
            sincospif(-2.0f * (float)t * (float)(kt-1) / (float)NT, &st, &ct);
            float2 et = make_float2(ct, st);
            #pragma unroll
            for (int kh = 0; kh < 3; kh++){
                float sh, ch;
                sincospif(-2.0f * (float)h * (float)(kh-1) / (float)NH, &sh, &ch);
                float2 e = cmul(et, make_float2(ch, sh));
                float ka = Ak[((c*3+kt)*3+kh)*3+kw];
                float kb = Bk[((c*3+kt)*3+kh)*3+kw];
                aA.x += ka*e.x; aA.y += ka*e.y;
                aB.x += kb*e.x; aB.y += kb*e.y;
            }
        }
        g_QA[i] = aA; g_QB[i] = aB;
        return;
    }

    int blk = blockIdx.x;
    int b = blk >> 10, t = (blk >> 6) & 15, h = blk & 63;
    size_t xbase = (size_t)blk * PLANE;

    const float4* dW4 = reinterpret_cast<const float4*>(dW);
    #pragma unroll
    for (int i = 0; i < 4; i++){
        int j = tid + i*256;
        Ws4[(j >> 4)*17 + (j & 15)] = dW4[j];
    }
    #pragma unroll
    for (int i = 0; i < 16; i++){
        int idx = tid + i*256;           // idx = w*64 + c
        xs[(idx >> 6)*65 + (idx & 63)] = x[xbase + idx];
    }
    __syncthreads();

    int w   = tid & 63;
    int dg  = tid >> 6;
    int ddb = dg << 4;

    ull acc[8];
    #pragma unroll
    for (int j = 0; j < 8; j++) acc[j] = pk2(__ldg(&db[ddb+2*j]), __ldg(&db[ddb+2*j+1]));

    const float* xrow = &xs[w*65];
    #pragma unroll 4
    for (int c = 0; c < 64; c++){
        float xv = xrow[c];
        ull xp = pk2(xv, xv);
        const float4* wr = &Ws4[c*17 + dg*4];
        float4 w0 = wr[0], w1 = wr[1], w2 = wr[2], w3 = wr[3];
        acc[0] = ffma2(xp, pk2(w0.x, w0.y), acc[0]);
        acc[1] = ffma2(xp, pk2(w0.z, w0.w), acc[1]);
        acc[2] = ffma2(xp, pk2(w1.x, w1.y), acc[2]);
        acc[3] = ffma2(xp, pk2(w1.z, w1.w), acc[3]);
        acc[4] = ffma2(xp, pk2(w2.x, w2.y), acc[4]);
        acc[5] = ffma2(xp, pk2(w2.z, w2.w), acc[5]);
        acc[6] = ffma2(xp, pk2(w3.x, w3.y), acc[6]);
        acc[7] = ffma2(xp, pk2(w3.z, w3.w), acc[7]);
    }

    #pragma unroll
    for (int jj = 0; jj < 8; jj++){
        float2 dp = upk2(acc[jj]);
        #pragma unroll
        for (int k = 0; k < 2; k++){
            int ch = ddb + 2*jj + k;
            float dv = k ? dp.y : dp.x;
            float delta = softplusf_(dv);
            float xv = xs[w*65 + ch];
            float gv = sigmoidf_(__ldg(&fb[ch]) + __ldg(&fs[ch]) * xv);
            float uv = sigmoidf_(__ldg(&ib[ch]) + __ldg(&isc[ch]) * xv) * delta;
            size_t o = (((size_t)(b*NC + ch)*NT + t) * PLANE) + h*64 + w;
            g_gu[o] = __floats2half2_rn(gv, uv);
        }
    }
}

// ============ K2p: paired real 2D FFT (radix-8) + Hermitian unpack =========
__global__ __launch_bounds__(256) void k2p(){
    __shared__ float sre[64*SROW];
    __shared__ float sim[64*SROW];
    int blk = blockIdx.x;                // (b,t,cp)
    int cp = blk & 31, t = (blk >> 5) & 15, b = blk >> 9;
    int c0 = cp*2;
    size_t base0 = ((size_t)((b*NC + c0)*NT + t)) * PLANE;     // X planes
    size_t base1 = base0 + (size_t)NT*PLANE;
    size_t base2 = ((size_t)((b*32 + cp)*NT + t)) * PLANE;     // xT2 plane
    int tid = threadIdx.x;

    #pragma unroll
    for (int i = 0; i < 16; i++){
        int idx = tid + i*256; int h = idx>>6, w = idx&63;
        float2 v = g_xT2[base2 + idx];
        int a = h*SROW + swz(w);
        sre[a] = v.x;
        sim[a] = v.y;
    }
    __syncthreads();

    fft2d_smem<1>(sre, sim, tid);

    // X0 = (Z[k]+conj(Z[-k]))/2, X1 = (Z[k]-conj(Z[-k]))/(2i)
    #pragma unroll
    for (int i = 0; i < 16; i++){
        int idx = tid + i*256; int kh = idx>>6, kw = idx&63;
        int mh = (NH - kh) & 63, mw = (NW - kw) & 63;
        int a  = kh*SROW + swz(kw);
        int m  = mh*SROW + swz(mw);
        float zr = sre[a], zi = sim[a];
        float mr = sre[m], mi = sim[m];
        g_X[base0 + idx] = make_float2(0.5f*(zr + mr), 0.5f*(zi - mi));
        g_X[base1 + idx] = make_float2(0.5f*(zi + mi), 0.5f*(mr - zr));
    }
}

// ============ K3: FFT16 over T + gated scan + iFFT16 (in place) ============
// R13 form (local optimum) + gu load software-pipelined by one iteration.
__global__ __launch_bounds__(256, 4) void k3(){
    __shared__ float2 sQA[192];          // [t][h'][kw]
    __shared__ float2 sQB[192];
    int blk = blockIdx.x;
    int tid = threadIdx.x;
    int hwblk = blk & 15;
    int c = (blk >> 4) & 63;
    int b = blk >> 10;
    int hw = hwblk*256 + tid;
    int w  = hw & 63;
    int hp = tid >> 6;
    int h0 = hwblk * 4;

    if (tid < 192){
        int kw = tid % 3, hh = (tid/3) & 3, t = tid / 12;
        int gidx = ((c*NT + t)*NH + (h0 + hh))*3 + kw;
        sQA[tid] = g_QA[gidx];
        sQB[tid] = g_QB[gidx];
    }
    __syncthreads();

    float sw, cw;
    sincospif(2.0f * (float)w / (float)NW, &sw, &cw);
    float2 ep = make_float2(cw,  sw);
    float2 em = make_float2(cw, -sw);

    size_t xbase = ((size_t)(b*NC + c) * NT) * PLANE + hw;

    float2 v[16];
    #pragma unroll
    for (int t = 0; t < 16; t++) v[t] = g_X[xbase + (size_t)t*PLANE];

    __half2 gun = g_gu[xbase];           // prefetch t=0 (overlaps fft16)
    fft16<1>(v);

    float2 hst = make_float2(0.f, 0.f);
    #pragma unroll
    for (int t = 0; t < 16; t++){
        float2 gu = __half22float2(gun);
        if (t < 15) gun = g_gu[xbase + (size_t)(t+1)*PLANE];   // prefetch next
        int qb = t*12 + hp*3;
        float2 af = cadd(cadd(cmul(sQA[qb], ep), sQA[qb+1]), cmul(sQA[qb+2], em));
        float2 bf = cadd(cadd(cmul(sQB[qb], ep), sQB[qb+1]), cmul(sQB[qb+2], em));
        float2 a  = make_float2(af.x*gu.x, af.y*gu.x);
        float2 bb = cmul(bf, v[t]);
        bb.x *= gu.y; bb.y *= gu.y;
        hst = cadd(cmul(a, hst), bb);
        v[t] = hst;
    }
    fft16<-1>(v);
    #pragma unroll
    for (int t = 0; t < 16; t++) g_X[xbase + (size_t)t*PLANE] = v[t];
}

// ============ K4p: paired inverse 2D FFT (radix-8) -> yT2 pairs ============
__global__ __launch_bounds__(256) void k4p(){
    __shared__ float sre[64*SROW];
    __shared__ float sim[64*SROW];
    int blk = blockIdx.x;
    int cp = blk & 31, t = (blk >> 5) & 15, b = blk >> 9;
    int c0 = cp*2;
    size_t base0 = ((size_t)((b*NC + c0)*NT + t)) * PLANE;
    size_t base1 = base0 + (size_t)NT*PLANE;
    size_t base2 = ((size_t)((b*32 + cp)*NT + t)) * PLANE;     // yT2 plane
    int tid = threadIdx.x;

    // load + Hermitian projection (mirror reads are L2 hits)
    #pragma unroll
    for (int i = 0; i < 16; i++){
        int idx = tid + i*256; int kh = idx>>6, kw = idx&63;
        int mh = (NH - kh) & 63, mw = (NW - kw) & 63;
        int midx = mh*64 + mw;
        float2 A  = g_X[base0 + idx];
        float2 Bm = g_X[base0 + midx];
        float2 C  = g_X[base1 + idx];
        float2 Dm = g_X[base1 + midx];
        int a = kh*SROW + swz(kw);
        sre[a] = A.x + Bm.x - C.y + Dm.y;
        sim[a] = A.y - Bm.y + C.x + Dm.x;
    }
    __syncthreads();

    fft2d_smem<-1>(sre, sim, tid);

    const float sc = 0.5f / 65536.0f;    // 1/(2*T*H*W): Herm 1/2 folded in
    #pragma unroll
    for (int i = 0; i < 16; i++){
        int idx = tid + i*256; int h = idx>>6, w = idx&63;
        int a = h*SROW + swz(w);
        g_xT2[base2 + idx] = make_float2(sre[a] * sc, sim[a] * sc);
    }
}

// ============ K5: transpose yT2 (b,cp,t,h,w) -> out (b,t,h,w,c) ============
__global__ __launch_bounds__(256) void k5(float* __restrict__ out){
    __shared__ float2 s2[32*65];
    int blk = blockIdx.x;                // (b,t,h)
    int b = blk >> 10, t = (blk >> 6) & 15, h = blk & 63;
    int tid = threadIdx.x;
    #pragma unroll
    for (int i = 0; i < 8; i++){
        int idx = tid + i*256;           // idx = cp*64 + w
        int cp = idx >> 6, w = idx & 63;
        s2[cp*65 + w] = g_xT2[(((size_t)(b*32 + cp)*NT + t) * PLANE) + h*64 + w];
    }
    __syncthreads();
    float2* out2 = reinterpret_cast<float2*>(out);
    size_t obase2 = (size_t)blk * 2048;
    #pragma unroll
    for (int i = 0; i < 8; i++){
        int idx = tid + i*256;           // idx = w*32 + cp
        int w = idx >> 5, cp = idx & 31;
        out2[obase2 + (size_t)w*32 + cp] = s2[cp*65 + w];
    }
}

// ---------------- side-stream objects (host-side, created at static init) --
struct SideStream {
    cudaStream_t s1 = nullptr;
    cudaEvent_t  e0 = nullptr, e1 = nullptr;
    bool ok = false;
    SideStream(){
        ok = (cudaStreamCreateWithFlags(&s1, cudaStreamNonBlocking) == cudaSuccess)
          && (cudaEventCreateWithFlags(&e0, cudaEventDisableTiming) == cudaSuccess)
          && (cudaEventCreateWithFlags(&e1, cudaEventDisableTiming) == cudaSuccess);
    }
};
static SideStream g_ss;

// ===========================================================================
extern "C" void kernel_launch(void* const* d_in, const int* in_sizes, int n_in,
                              void* d_out, int out_size)
{
    const float* x   = (const float*)d_in[0];
    const float* Ak  = (const float*)d_in[1];
    const float* Bk  = (const float*)d_in[2];
    const float* fb  = (const float*)d_in[3];
    const float* fs  = (const float*)d_in[4];
    const float* ib  = (const float*)d_in[5];
    const float* isc = (const float*)d_in[6];
    const float* dW  = (const float*)d_in[7];
    const float* db  = (const float*)d_in[8];
    float* out = (float*)d_out;

    if (g_ss.ok){
        // fork: k1b (+merged k0) depends only on inputs; overlap with t0/k2p
        cudaEventRecord(g_ss.e0, 0);
        cudaStreamWaitEvent(g_ss.s1, g_ss.e0, 0);
        k1b<<<2816, 256, 0, g_ss.s1>>>(x, dW, db, ib, isc, fb, fs, Ak, Bk);
        cudaEventRecord(g_ss.e1, g_ss.s1);

        t0 <<<2048, 256>>>(x);
        k2p<<<1024, 256>>>();
        cudaStreamWaitEvent(0, g_ss.e1, 0);   // join before k3 (needs gu, QA/QB)
    } else {
        k1b<<<2816, 256>>>(x, dW, db, ib, isc, fb, fs, Ak, Bk);
        t0 <<<2048, 256>>>(x);
        k2p<<<1024, 256>>>();
    }
    k3 <<<2048, 256>>>();
    k4p<<<1024, 256>>>();
    k5 <<<2048, 256>>>(out);
}

// round 17
// speedup vs baseline: 1.0830x; 1.0295x over previous
#include <cuda_runtime.h>
#include <cuda_bf16.h>
#include <cuda_fp16.h>

// Problem dims
#define NBATCH 2
#define NC 64
#define NT 16
#define NH 64
#define NW 64
#define PLANE 4096                    // NH*NW
#define SROW 72                       // padded smem row stride (floats)

typedef unsigned long long ull;

// ---------------- scratch (__device__ globals; no runtime allocation) ------
__device__ float2  g_QA[NC * NT * NH * 3];                   // 1.5 MB
__device__ float2  g_QB[NC * NT * NH * 3];                   // 1.5 MB
__device__ __half2 g_gu [(size_t)NBATCH * NC * NT * PLANE];  // 33.5 MB fp16 (g,u)
__device__ float2  g_xT2[(size_t)NBATCH * 32 * NT * PLANE];  // 33.5 MB (x pairs, then y pairs)
__device__ float2  g_X  [(size_t)NBATCH * NC * NT * PLANE];  // 67 MB (X then h_f in place)

// ---------------- PDL primitives -------------------------------------------
__device__ __forceinline__ void gdc_trigger(){
    asm volatile("griddepcontrol.launch_dependents;");
}
__device__ __forceinline__ void gdc_wait(){
    asm volatile("griddepcontrol.wait;" ::: "memory");
}

// ---------------- twiddle table (uniform compile-time indices only) --------
__constant__ float2 gW64[32] = {
    { 1.00000000f, -0.00000000f}, { 0.99518473f, -0.09801714f},
    { 0.98078528f, -0.19509032f}, { 0.95694034f, -0.29028468f},
    { 0.92387953f, -0.38268343f}, { 0.88192126f, -0.47139674f},
    { 0.83146961f, -0.55557023f}, { 0.77301045f, -0.63439328f},
    { 0.70710678f, -0.70710678f}, { 0.63439328f, -0.77301045f},
    { 0.55557023f, -0.83146961f}, { 0.47139674f, -0.88192126f},
    { 0.38268343f, -0.92387953f}, { 0.29028468f, -0.95694034f},
    { 0.19509032f, -0.98078528f}, { 0.09801714f, -0.99518473f},
    { 0.00000000f, -1.00000000f}, {-0.09801714f, -0.99518473f},
    {-0.19509032f, -0.98078528f}, {-0.29028468f, -0.95694034f},
    {-0.38268343f, -0.92387953f}, {-0.47139674f, -0.88192126f},
    {-0.55557023f, -0.83146961f}, {-0.63439328f, -0.77301045f},
    {-0.70710678f, -0.70710678f}, {-0.77301045f, -0.63439328f},
    {-0.83146961f, -0.55557023f}, {-0.88192126f, -0.47139674f},
    {-0.92387953f, -0.38268343f}, {-0.95694034f, -0.29028468f},
    {-0.98078528f, -0.19509032f}, {-0.99518473f, -0.09801714f}
};

// ---------------- complex helpers ------------------------------------------
__device__ __forceinline__ float2 cadd(float2 a, float2 b){ return make_float2(a.x+b.x, a.y+b.y); }
__device__ __forceinline__ float2 csub(float2 a, float2 b){ return make_float2(a.x-b.x, a.y-b.y); }
__device__ __forceinline__ float2 cmul(float2 a, float2 b){
    return make_float2(a.x*b.x - a.y*b.y, a.x*b.y + a.y*b.x);
}

template<int SGN>
__device__ __forceinline__ float2 tw64c(int i){       // constant table, uniform idx
    float2 t = gW64[i];
    if (SGN < 0) t.y = -t.y;
    return t;
}

// padded column address: avoids bank conflicts for stride-8 AND contiguous-8
__device__ __forceinline__ int swz(int w){ return w + (w >> 3); }

// ---------------- f32x2 packed FMA helpers (GEMV only) ---------------------
__device__ __forceinline__ ull pk2(float a, float b){
    ull r; asm("mov.b64 %0, {%1,%2};" : "=l"(r) : "f"(a), "f"(b)); return r;
}
__device__ __forceinline__ float2 upk2(ull v){
    float2 f; asm("mov.b64 {%0,%1}, %2;" : "=f"(f.x), "=f"(f.y) : "l"(v)); return f;
}
__device__ __forceinline__ ull ffma2(ull a, ull b, ull c){
    ull d; asm("fma.rn.f32x2 %0, %1, %2, %3;" : "=l"(d) : "l"(a), "l"(b), "l"(c)); return d;
}

// ---------------- register FFT8 (natural in/out) ---------------------------
template<int SGN>
__device__ __forceinline__ void fft8(float2 v[8]){
    #pragma unroll
    for (int half = 4; half >= 1; half >>= 1){
        #pragma unroll
        for (int base = 0; base < 8; base += 2*half){
            #pragma unroll
            for (int j = 0; j < half; j++){
                float2 a = v[base+j], b = v[base+j+half];
                v[base+j] = cadd(a, b);
                v[base+j+half] = cmul(csub(a, b), tw64c<SGN>(j * (32/half)));
            }
        }
    }
    float2 t;
    t=v[1]; v[1]=v[4]; v[4]=t;     // 3-bit reversal
    t=v[3]; v[3]=v[6]; v[6]=t;
}

// ---------------- register FFT16 (natural in, natural out) -----------------
template<int SGN>
__device__ __forceinline__ void fft16(float2 v[16]){
    #pragma unroll
    for (int half = 8; half >= 1; half >>= 1){
        #pragma unroll
        for (int base = 0; base < 16; base += 2*half){
            #pragma unroll
            for (int j = 0; j < half; j++){
                float2 a = v[base+j], b = v[base+j+half];
                v[base+j] = cadd(a, b);
                v[base+j+half] = cmul(csub(a, b), tw64c<SGN>(j * (32/half)));
            }
        }
    }
    float2 t;
    t=v[1];  v[1]=v[8];   v[8]=t;
    t=v[2];  v[2]=v[4];   v[4]=t;
    t=v[3];  v[3]=v[12];  v[12]=t;
    t=v[5];  v[5]=v[10];  v[10]=t;
    t=v[7];  v[7]=v[14];  v[14]=t;
    t=v[11]; v[11]=v[13]; v[13]=t;
}

// ---------------- 2D FFT64x64 in smem via radix-8 x radix-8 ----------------
template<int SGN>
__device__ __forceinline__ void fft2d_smem(float* sre, float* sim, int tid){
    const float sgn = (SGN > 0) ? -1.0f : 1.0f;
    float ss, cc;

    // ---- row pass: 8 threads per row (same warp), rows tid>>3, +32 --------
    int n2 = tid & 7, rg = tid >> 3;
    sincospif(sgn * (float)n2 / 32.0f, &ss, &cc);
    float2 twn2 = make_float2(cc, ss);           // W64^{±n2}
    #pragma unroll
    for (int it = 0; it < 2; it++){
        int row = it*32 + rg;
        float* rre = sre + row*SROW;
        float* rim = sim + row*SROW;
        float2 v[8];
        #pragma unroll
        for (int j = 0; j < 8; j++){
            int cI = swz(8*j + n2);
            v[j] = make_float2(rre[cI], rim[cI]);
        }
        fft8<SGN>(v);
        {   // v[k1] *= W64^{±n2*k1}
            float2 w = twn2;
            v[1] = cmul(v[1], w);
            #pragma unroll
            for (int k = 2; k < 8; k++){ w = cmul(w, twn2); v[k] = cmul(v[k], w); }
        }
        __syncwarp();
        #pragma unroll
        for (int j = 0; j < 8; j++){                 // B[n2][k1=j] at col 8*n2+j
            int cI = swz(8*n2 + j);
            rre[cI] = v[j].x; rim[cI] = v[j].y;
        }
        __syncwarp();
        #pragma unroll
        for (int j = 0; j < 8; j++){                 // thread acts as k1=n2
            int cI = swz(8*j + n2);                  // B[n2'=j][k1]
            v[j] = make_float2(rre[cI], rim[cI]);
        }
        fft8<SGN>(v);
        #pragma unroll
        for (int j = 0; j < 8; j++){                 // X[8*k2+k1], k2=j
            int cI = swz(8*j + n2);
            rre[cI] = v[j].x; rim[cI] = v[j].y;
        }
    }
    __syncthreads();

    // ---- column pass: cols across the warp (tid&31), n2 = tid>>5 ----------
    int cn2 = tid >> 5, cg = tid & 31;
    sincospif(sgn * (float)cn2 / 32.0f, &ss, &cc);
    float2 twc = make_float2(cc, ss);
    #pragma unroll
    for (int it = 0; it < 2; it++){
        int cph = swz(it*32 + cg);
        float2 v[8];
        #pragma unroll
        for (int j = 0; j < 8; j++){
            int r = 8*j + cn2;
            v[j] = make_float2(sre[r*SROW + cph], sim[r*SROW + cph]);
        }
        fft8<SGN>(v);
        {
            float2 w = twc;
            v[1] = cmul(v[1], w);
            #pragma unroll
            for (int k = 2; k < 8; k++){ w = cmul(w, twc); v[k] = cmul(v[k], w); }
        }
        __syncthreads();
        #pragma unroll
        for (int j = 0; j < 8; j++){                 // B at row 8*cn2+j
            int r = 8*cn2 + j;
            sre[r*SROW + cph] = v[j].x; sim[r*SROW + cph] = v[j].y;
        }
        __syncthreads();
        #pragma unroll
        for (int j = 0; j < 8; j++){                 // rows 8*j+cn2 (exclusive)
            int r = 8*j + cn2;
            v[j] = make_float2(sre[r*SROW + cph], sim[r*SROW + cph]);
        }
        fft8<SGN>(v);
        #pragma unroll
        for (int j = 0; j < 8; j++){
            int r = 8*j + cn2;
            sre[r*SROW + cph] = v[j].x; sim[r*SROW + cph] = v[j].y;
        }
    }
    __syncthreads();
}

__device__ __forceinline__ float sigmoidf_(float v){ return 1.0f / (1.0f + __expf(-v)); }
__device__ __forceinline__ float softplusf_(float v){
    return fmaxf(v, 0.0f) + log1pf(__expf(-fabsf(v)));
}

// ============ T0: transpose x (b,t,h,w,c) -> xT2 (b,cp,t,h,w) float2 pairs =
__global__ __launch_bounds__(256) void t0(const float* __restrict__ x){
    __shared__ float s[64*65];           // s[c][w]
    gdc_trigger();                       // let k2p launch early (it gdc_waits)
    int blk = blockIdx.x;                // (b,t,h)
    int b = blk >> 10, t = (blk >> 6) & 15, h = blk & 63;
    size_t xbase = (size_t)blk * PLANE;
    int tid = threadIdx.x;

    #pragma unroll
    for (int i = 0; i < 16; i++){
        int idx = tid + i*256;           // idx = w*64 + c
        s[(idx & 63)*65 + (idx >> 6)] = x[xbase + idx];
    }
    __syncthreads();
    #pragma unroll
    for (int i = 0; i < 8; i++){
        int idx = tid + i*256;           // idx = cp*64 + w  (cp 0..31)
        int cp = idx >> 6, w = idx & 63;
        g_xT2[(((size_t)(b*32 + cp)*NT + t) * PLANE) + h*64 + w] =
            make_float2(s[(2*cp)*65 + w], s[(2*cp+1)*65 + w]);
    }
}

// ============ K1b: delta GEMV + gates -> fp16 gu  (+ merged K0 tail) =======
__global__ __launch_bounds__(256) void k1b(
    const float* __restrict__ x,  const float* __restrict__ dW,
    const float* __restrict__ db, const float* __restrict__ ib,
    const float* __restrict__ isc, const float* __restrict__ fb,
    const float* __restrict__ fs, const float* __restrict__ Ak,
    const float* __restrict__ Bk)
{
    __shared__ float  xs[64*65];         // xs[w][c]
    __shared__ float4 Ws4[64*17];        // Ws4[c][q]
    int tid = threadIdx.x;

    // ---- merged K0: blocks 2048..2815 build Q tables ----
    if (blockIdx.x >= 2048){
        int i = (blockIdx.x - 2048)*256 + tid;     // < 196608 = 64*16*64*3
        int kw = i % 3, h = (i/3) % NH, t = (i/192) % NT, c = i/(192*NT);
        float2 aA = make_float2(0.f,0.f), aB = make_float2(0.f,0.f);
        #pragma unroll
        for (int kt = 0; kt < 3; kt++){
            float st, ct;
            sincospif(-2.0f * (float)t * (float)(kt-1) / (float)NT, &st, &ct);
            float2 et = make_float2(ct, st);
            #pragma unroll
            for (int kh = 0; kh < 3; kh++){
                float sh, ch;
                sincospif(-2.0f * (float)h * (float)(kh-1) / (float)NH, &sh, &ch);
                float2 e = cmul(et, make_float2(ch, sh));
                float ka = Ak[((c*3+kt)*3+kh)*3+kw];
                float kb = Bk[((c*3+kt)*3+kh)*3+kw];
                aA.x += ka*e.x; aA.y += ka*e.y;
                aB.x += kb*e.x; aB.y += kb*e.y;
            }
        }
        g_QA[i] = aA; g_QB[i] = aB;
        return;
    }

    int blk = blockIdx.x;
    int b = blk >> 10, t = (blk >> 6) & 15, h = blk & 63;
    size_t xbase = (size_t)blk * PLANE;

    const float4* dW4 = reinterpret_cast<const float4*>(dW);
    #pragma unroll
    for (int i = 0; i < 4; i++){
        int j = tid + i*256;
        Ws4[(j >> 4)*17 + (j & 15)] = dW4[j];
    }
    #pragma unroll
    for (int i = 0; i < 16; i++){
        int idx = tid + i*256;           // idx = w*64 + c
        xs[(idx >> 6)*65 + (idx & 63)] = x[xbase + idx];
    }
    __syncthreads();

    int w   = tid & 63;
    int dg  = tid >> 6;
    int ddb = dg << 4;

    ull acc[8];
    #pragma unroll
    for (int j = 0; j < 8; j++) acc[j] = pk2(__ldg(&db[ddb+2*j]), __ldg(&db[ddb+2*j+1]));

    const float* xrow = &xs[w*65];
    #pragma unroll 4
    for (int c = 0; c < 64; c++){
        float xv = xrow[c];
        ull xp = pk2(xv, xv);
        const float4* wr = &Ws4[c*17 + dg*4];
        float4 w0 = wr[0], w1 = wr[1], w2 = wr[2], w3 = wr[3];
        acc[0] = ffma2(xp, pk2(w0.x, w0.y), acc[0]);
        acc[1] = ffma2(xp, pk2(w0.z, w0.w), acc[1]);
        acc[2] = ffma2(xp, pk2(w1.x, w1.y), acc[2]);
        acc[3] = ffma2(xp, pk2(w1.z, w1.w), acc[3]);
        acc[4] = ffma2(xp, pk2(w2.x, w2.y), acc[4]);
        acc[5] = ffma2(xp, pk2(w2.z, w2.w), acc[5]);
        acc[6] = ffma2(xp, pk2(w3.x, w3.y), acc[6]);
        acc[7] = ffma2(xp, pk2(w3.z, w3.w), acc[7]);
    }

    #pragma unroll
    for (int jj = 0; jj < 8; jj++){
        float2 dp = upk2(acc[jj]);
        #pragma unroll
        for (int k = 0; k < 2; k++){
            int ch = ddb + 2*jj + k;
            float dv = k ? dp.y : dp.x;
            float delta = softplusf_(dv);
            float xv = xs[w*65 + ch];
            float gv = sigmoidf_(__ldg(&fb[ch]) + __ldg(&fs[ch]) * xv);
            float uv = sigmoidf_(__ldg(&ib[ch]) + __ldg(&isc[ch]) * xv) * delta;
            size_t o = (((size_t)(b*NC + ch)*NT + t) * PLANE) + h*64 + w;
            g_gu[o] = __floats2half2_rn(gv, uv);
        }
    }
}

// ============ K2p: paired real 2D FFT (radix-8) + Hermitian unpack =========
__global__ __launch_bounds__(256) void k2p(){
    __shared__ float sre[64*SROW];
    __shared__ float sim[64*SROW];
    gdc_trigger();                       // let k3 launch early
    int blk = blockIdx.x;                // (b,t,cp)
    int cp = blk & 31, t = (blk >> 5) & 15, b = blk >> 9;
    int c0 = cp*2;
    size_t base0 = ((size_t)((b*NC + c0)*NT + t)) * PLANE;     // X planes
    size_t base1 = base0 + (size_t)NT*PLANE;
    size_t base2 = ((size_t)((b*32 + cp)*NT + t)) * PLANE;     // xT2 plane
    int tid = threadIdx.x;

    gdc_wait();                          // t0's xT2 must be complete
    #pragma unroll
    for (int i = 0; i < 16; i++){
        int idx = tid + i*256; int h = idx>>6, w = idx&63;
        float2 v = g_xT2[base2 + idx];
        int a = h*SROW + swz(w);
        sre[a] = v.x;
        sim[a] = v.y;
    }
    __syncthreads();

    fft2d_smem<1>(sre, sim, tid);

    // X0 = (Z[k]+conj(Z[-k]))/2, X1 = (Z[k]-conj(Z[-k]))/(2i)
    #pragma unroll
    for (int i = 0; i < 16; i++){
        int idx = tid + i*256; int kh = idx>>6, kw = idx&63;
        int mh = (NH - kh) & 63, mw = (NW - kw) & 63;
        int a  = kh*SROW + swz(kw);
        int m  = mh*SROW + swz(mw);
        float zr = sre[a], zi = sim[a];
        float mr = sre[m], mi = sim[m];
        g_X[base0 + idx] = make_float2(0.5f*(zr + mr), 0.5f*(zi - mi));
        g_X[base1 + idx] = make_float2(0.5f*(zi + mi), 0.5f*(mr - zr));
    }
}

// ============ K3: FFT16 over T + gated scan + iFFT16 (in place) ============
__global__ __launch_bounds__(256, 4) void k3(){
    __shared__ float2 sQA[192];          // [t][h'][kw]
    __shared__ float2 sQB[192];
    gdc_trigger();                       // let k4p launch early
    int blk = blockIdx.x;
    int tid = threadIdx.x;
    int hwblk = blk & 15;
    int c = (blk >> 4) & 63;
    int b = blk >> 10;
    int hw = hwblk*256 + tid;
    int w  = hw & 63;
    int hp = tid >> 6;
    int h0 = hwblk * 4;

    // prologue: tables from k1b (event-joined at launch; safe pre-wait)
    if (tid < 192){
        int kw = tid % 3, hh = (tid/3) & 3, t = tid / 12;
        int gidx = ((c*NT + t)*NH + (h0 + hh))*3 + kw;
        sQA[tid] = g_QA[gidx];
        sQB[tid] = g_QB[gidx];
    }
    __syncthreads();

    float sw, cw;
    sincospif(2.0f * (float)w / (float)NW, &sw, &cw);
    float2 ep = make_float2(cw,  sw);
    float2 em = make_float2(cw, -sw);

    size_t xbase = ((size_t)(b*NC + c) * NT) * PLANE + hw;

    gdc_wait();                          // k2p's X must be complete
    float2 v[16];
    #pragma unroll
    for (int t = 0; t < 16; t++) v[t] = g_X[xbase + (size_t)t*PLANE];

    __half2 gun = g_gu[xbase];           // prefetch t=0 (overlaps fft16)
    fft16<1>(v);

    float2 hst = make_float2(0.f, 0.f);
    #pragma unroll
    for (int t = 0; t < 16; t++){
        float2 gu = __half22float2(gun);
        if (t < 15) gun = g_gu[xbase + (size_t)(t+1)*PLANE];   // prefetch next
        int qb = t*12 + hp*3;
        float2 af = cadd(cadd(cmul(sQA[qb], ep), sQA[qb+1]), cmul(sQA[qb+2], em));
        float2 bf = cadd(cadd(cmul(sQB[qb], ep), sQB[qb+1]), cmul(sQB[qb+2], em));
        float2 a  = make_float2(af.x*gu.x, af.y*gu.x);
        float2 bb = cmul(bf, v[t]);
        bb.x *= gu.y; bb.y *= gu.y;
        hst = cadd(cmul(a, hst), bb);
        v[t] = hst;
    }
    fft16<-1>(v);
    #pragma unroll
    for (int t = 0; t < 16; t++) g_X[xbase + (size_t)t*PLANE] = v[t];
}

// ============ K4p: paired inverse 2D FFT (radix-8) -> yT2 pairs ============
__global__ __launch_bounds__(256) void k4p(){
    __shared__ float sre[64*SROW];
    __shared__ float sim[64*SROW];
    gdc_trigger();                       // let k5 launch early
    int blk = blockIdx.x;
    int cp = blk & 31, t = (blk >> 5) & 15, b = blk >> 9;
    int c0 = cp*2;
    size_t base0 = ((size_t)((b*NC + c0)*NT + t)) * PLANE;
    size_t base1 = base0 + (size_t)NT*PLANE;
    size_t base2 = ((size_t)((b*32 + cp)*NT + t)) * PLANE;     // yT2 plane
    int tid = threadIdx.x;

    gdc_wait();                          // k3's h_f must be complete
    // load + Hermitian projection (mirror reads are L2 hits)
    #pragma unroll
    for (int i = 0; i < 16; i++){
        int idx = tid + i*256; int kh = idx>>6, kw = idx&63;
        int mh = (NH - kh) & 63, mw = (NW - kw) & 63;
        int midx = mh*64 + mw;
        float2 A  = g_X[base0 + idx];
        float2 Bm = g_X[base0 + midx];
        float2 C  = g_X[base1 + idx];
        float2 Dm = g_X[base1 + midx];
        int a = kh*SROW + swz(kw);
        sre[a] = A.x + Bm.x - C.y + Dm.y;
        sim[a] = A.y - Bm.y + C.x + Dm.x;
    }
    __syncthreads();

    fft2d_smem<-1>(sre, sim, tid);

    const float sc = 0.5f / 65536.0f;    // 1/(2*T*H*W): Herm 1/2 folded in
    #pragma unroll
    for (int i = 0; i < 16; i++){
        int idx = tid + i*256; int h = idx>>6, w = idx&63;
        int a = h*SROW + swz(w);
        g_xT2[base2 + idx] = make_float2(sre[a] * sc, sim[a] * sc);
    }
}

// ============ K5: transpose yT2 (b,cp,t,h,w) -> out (b,t,h,w,c) ============
__global__ __launch_bounds__(256) void k5(float* __restrict__ out){
    __shared__ float2 s2[32*65];
    int blk = blockIdx.x;                // (b,t,h)
    int b = blk >> 10, t = (blk >> 6) & 15, h = blk & 63;
    int tid = threadIdx.x;
    gdc_wait();                          // k4p's yT2 must be complete
    #pragma unroll
    for (int i = 0; i < 8; i++){
        int idx = tid + i*256;           // idx = cp*64 + w
        int cp = idx >> 6, w = idx & 63;
        s2[cp*65 + w] = g_xT2[(((size_t)(b*32 + cp)*NT + t) * PLANE) + h*64 + w];
    }
    __syncthreads();
    float2* out2 = reinterpret_cast<float2*>(out);
    size_t obase2 = (size_t)blk * 2048;
    #pragma unroll
    for (int i = 0; i < 8; i++){
        int idx = tid + i*256;           // idx = w*32 + cp
        int w = idx >> 5, cp = idx & 31;
        out2[obase2 + (size_t)w*32 + cp] = s2[cp*65 + w];
    }
}

// ---------------- side-stream objects (host-side, created at static init) --
struct SideStream {
    cudaStream_t s1 = nullptr;
    cudaEvent_t  e0 = nullptr, e1 = nullptr;
    bool ok = false;
    SideStream(){
        ok = (cudaStreamCreateWithFlags(&s1, cudaStreamNonBlocking) == cudaSuccess)
          && (cudaEventCreateWithFlags(&e0, cudaEventDisableTiming) == cudaSuccess)
          && (cudaEventCreateWithFlags(&e1, cudaEventDisableTiming) == cudaSuccess);
    }
};
static SideStream g_ss;

// PDL launch helper: secondary may begin launching while its in-stream
// predecessor is still draining; kernel-side griddepcontrol.wait provides
// the data dependency.
template <typename... Args>
static inline void launch_pdl(void (*kern)(Args...), int grid,
                              cudaStream_t s, Args... args){
    cudaLaunchConfig_t cfg = {};
    cfg.gridDim  = dim3((unsigned)grid, 1, 1);
    cfg.blockDim = dim3(256, 1, 1);
    cfg.dynamicSmemBytes = 0;
    cfg.stream = s;
    cudaLaunchAttribute at[1];
    at[0].id = cudaLaunchAttributeProgrammaticStreamSerialization;
    at[0].val.programmaticStreamSerializationAllowed = 1;
    cfg.attrs = at; cfg.numAttrs = 1;
    cudaLaunchKernelEx(&cfg, kern, args...);
}

// ===========================================================================
extern "C" void kernel_launch(void* const* d_in, const int* in_sizes, int n_in,
                              void* d_out, int out_size)
{
    const float* x   = (const float*)d_in[0];
    const float* Ak  = (const float*)d_in[1];
    const float* Bk  = (const float*)d_in[2];
    const float* fb  = (const float*)d_in[3];
    const float* fs  = (const float*)d_in[4];
    const float* ib  = (const float*)d_in[5];
    const float* isc = (const float*)d_in[6];
    const float* dW  = (const float*)d_in[7];
    const float* db  = (const float*)d_in[8];
    float* out = (float*)d_out;

    if (g_ss.ok){
        // fork: k1b (+merged k0) depends only on inputs; overlap with t0/k2p
        cudaEventRecord(g_ss.e0, 0);
        cudaStreamWaitEvent(g_ss.s1, g_ss.e0, 0);
        k1b<<<2816, 256, 0, g_ss.s1>>>(x, dW, db, ib, isc, fb, fs, Ak, Bk);
        cudaEventRecord(g_ss.e1, g_ss.s1);

        t0 <<<2048, 256>>>(x);
        launch_pdl(k2p, 1024, (cudaStream_t)0);
        cudaStreamWaitEvent(0, g_ss.e1, 0);   // join before k3 (needs gu, QA/QB)
        launch_pdl(k3, 2048, (cudaStream_t)0);
        launch_pdl(k4p, 1024, (cudaStream_t)0);
        launch_pdl(k5, 2048, (cudaStream_t)0, out);
    } else {
        k1b<<<2816, 256>>>(x, dW, db, ib, isc, fb, fs, Ak, Bk);
        t0 <<<2048, 256>>>(x);
        k2p<<<1024, 256>>>();
        k3 <<<2048, 256>>>();
        k4p<<<1024, 256>>>();
        k5 <<<2048, 256>>>(out);
    }
}